// round 15
// baseline (speedup 1.0000x reference)
#include <cuda_runtime.h>
#include <cuda_bf16.h>
#include <mma.h>
#include <cstdint>
#include <cstddef>

using namespace nvcuda;

#define BB 16
#define SEQ 512
#define HID 1024
#define C2 128          // 2*HEAD_SIZE
#define NHEADS 12
#define HS 64
#define ROWS (BB*SEQ)   // 8192
#define NEG_BIG 1000000000000.0f

// k1 smem strides: 136 bf16 = 272 B (16B-aligned rows, conflict-free LDSM)
#define AST 136
#define WST 136
#define KC  128                       // k-chunk
#define ABYTES (32 * AST * 2)         // 8704
#define WBYTES (KC * WST * 2)         // 34816
#define STAGE  (ABYTES + WBYTES)      // 43520
#define NSTG   2
#define K1_DYN (NSTG * STAGE)         // 87040

// ---- scratch (device globals) ----
__device__ __nv_bfloat16 g_ab[ROWS * HID];   // A bf16 (16 MB)
__device__ __nv_bfloat16 g_w1b[HID * C2];    // W1 bf16
__device__ __nv_bfloat16 g_qb[ROWS * HS];    // RoPE'd q, bf16
__device__ __nv_bfloat16 g_kb[ROWS * HS];    // RoPE'd k, bf16
__device__ float g_be[BB * NHEADS * SEQ];
__device__ float g_bo[BB * NHEADS * SEQ];

__device__ __forceinline__ uint32_t s2u(const void* p) {
    uint32_t a;
    asm("{ .reg .u64 t; cvta.to.shared.u64 t, %1; cvt.u32.u64 %0, t; }"
        : "=r"(a) : "l"(p));
    return a;
}
#define CP16(dst_u32, src_ptr) \
    asm volatile("cp.async.ca.shared.global [%0], [%1], 16;" \
                 :: "r"(dst_u32), "l"(src_ptr) : "memory")
#define CPCOMMIT() asm volatile("cp.async.commit_group;" ::: "memory")
#define CPWAIT1()  asm volatile("cp.async.wait_group 1;" ::: "memory")
#define CPWAIT0()  asm volatile("cp.async.wait_group 0;" ::: "memory")

__device__ __forceinline__ uint32_t packbf2(float a, float b) {
    __nv_bfloat162 h(__float2bfloat16(a), __float2bfloat16(b));
    return *(uint32_t*)&h;
}

// ========================================================================
// convAW v2: 8 floats/thread -> one 16B store.
// A: 8M floats = 4096 blocks; W1: 128K floats = 64 blocks.
// ========================================================================
__global__ void __launch_bounds__(256) convAW(const float4* __restrict__ A,
                                              const float4* __restrict__ W1) {
    int tid = threadIdx.x;
    size_t b = blockIdx.x;
    const float4* src;
    uint4* dst;
    size_t i;            // uint4 index in dst
    if (b < 4096) {
        i = b * 256 + tid;
        src = A;
        dst = (uint4*)g_ab;
    } else {
        i = (b - 4096) * 256 + tid;
        src = W1;
        dst = (uint4*)g_w1b;
    }
    float4 v0 = src[2 * i];
    float4 v1 = src[2 * i + 1];
    uint4 o;
    o.x = packbf2(v0.x, v0.y);
    o.y = packbf2(v0.z, v0.w);
    o.z = packbf2(v1.x, v1.y);
    o.w = packbf2(v1.z, v1.w);
    dst[i] = o;
}

// ========================================================================
// k1_gemm v4: K-chunk 128, 2-stage cp.async pipeline (8 chunks).
// Per chunk: sync -> issue(c+1) -> wait(c) -> sync -> 8x mma.
// ========================================================================
__global__ void __launch_bounds__(256, 2) k1_gemm(const float* __restrict__ b1,
                                                  const float* __restrict__ W2,
                                                  const float* __restrict__ b2) {
    extern __shared__ __align__(16) char sm[];
    float* xs = (float*)sm;                    // [32][128] f32, epilogue only
    __shared__ float W2s[128 * 24];
    __shared__ float b1s[128];
    __shared__ float b2s[24];

    int tid = threadIdx.x, w = tid >> 5, l = tid & 31;
    int row0 = blockIdx.x * 32;
    uint32_t sbase = s2u(sm);

    if (tid < 128) b1s[tid] = b1[tid];
    if (tid < 24)  b2s[tid] = b2[tid];
    for (int i = tid; i < 3072; i += 256) W2s[i] = W2[i];

    int wm = (w & 1) * 16;
    int wn = (w >> 1) * 32;

    wmma::fragment<wmma::accumulator, 16, 16, 16, float> acc[2];
    wmma::fill_fragment(acc[0], 0.0f);
    wmma::fill_fragment(acc[1], 0.0f);

    // A chunk: 32 rows x 128 k = 512 CP16 (2/thread)
    // W chunk: 128 rows x 128 c = 2048 CP16 (8/thread)
    auto issue = [&](int kc, int s) {
        uint32_t ab = sbase + (uint32_t)s * STAGE;
        uint32_t wb = ab + ABYTES;
#pragma unroll
        for (int s2 = 0; s2 < 2; ++s2) {
            int idx = tid + s2 * 256;
            int r = idx >> 4, seg = idx & 15;
            CP16(ab + (uint32_t)(r * AST + seg * 8) * 2,
                 g_ab + (size_t)(row0 + r) * HID + kc + seg * 8);
        }
#pragma unroll
        for (int s4 = 0; s4 < 8; ++s4) {
            int idx = tid + s4 * 256;
            int r = idx >> 4, seg = idx & 15;
            CP16(wb + (uint32_t)(r * WST + seg * 8) * 2,
                 g_w1b + (size_t)(kc + r) * C2 + seg * 8);
        }
        CPCOMMIT();
    };

    issue(0, 0);
    for (int c = 0; c < 8; ++c) {
        if (c > 0) __syncthreads();           // all warps done mma(c-1)
        if (c + 1 < 8) { issue((c + 1) * KC, (c + 1) & 1); CPWAIT1(); }
        else           { CPWAIT0(); }
        __syncthreads();                      // chunk c visible to all warps
        const __nv_bfloat16* Ab =
            (const __nv_bfloat16*)(sm + (c & 1) * STAGE);
        const __nv_bfloat16* Wb =
            (const __nv_bfloat16*)(sm + (c & 1) * STAGE + ABYTES);
#pragma unroll
        for (int ks = 0; ks < 8; ++ks) {
            wmma::fragment<wmma::matrix_a, 16, 16, 16, __nv_bfloat16, wmma::row_major> fa;
            wmma::load_matrix_sync(fa, Ab + wm * AST + ks * 16, AST);
#pragma unroll
            for (int nt = 0; nt < 2; ++nt) {
                wmma::fragment<wmma::matrix_b, 16, 16, 16, __nv_bfloat16, wmma::row_major> fb;
                wmma::load_matrix_sync(fb, Wb + ks * 16 * WST + wn + nt * 16, WST);
                wmma::mma_sync(acc[nt], fa, fb, acc[nt]);
            }
        }
    }
    __syncthreads();

    // ---- epilogue: frags -> xs, add b1 ----
    wmma::store_matrix_sync(xs + wm * C2 + wn,      acc[0], C2, wmma::mem_row_major);
    wmma::store_matrix_sync(xs + wm * C2 + wn + 16, acc[1], C2, wmma::mem_row_major);
    __syncthreads();
#pragma unroll
    for (int s = 0; s < 4; ++s) {
        int i = tid + s * 256;
        int r = i >> 5, c4 = i & 31;
        float4 v  = *(float4*)&xs[r * C2 + c4 * 4];
        float4 bv = *(float4*)&b1s[c4 * 4];
        v.x += bv.x; v.y += bv.y; v.z += bv.z; v.w += bv.w;
        *(float4*)&xs[r * C2 + c4 * 4] = v;
    }
    __syncthreads();

    // ---- RoPE: warp w owns rows w*4..w*4+3 ----
    float inv = exp2f(-(float)l * 0.41524101186091903f);
#pragma unroll
    for (int rr = 0; rr < 4; ++rr) {
        int r = w * 4 + rr;
        int row = row0 + r;
        int pos = row & 511;
        float4 xv = *(float4*)&xs[r * 128 + l * 4];
        float sn, cs;
        sincosf((float)pos * inv, &sn, &cs);
        float q0 = xv.x * cs - xv.z * sn;
        float q1 = xv.z * cs + xv.x * sn;
        float k0 = xv.y * cs - xv.w * sn;
        float k1 = xv.w * cs + xv.y * sn;
        ((__nv_bfloat162*)g_qb)[(size_t)row * 32 + l] =
            __nv_bfloat162(__float2bfloat16(q0), __float2bfloat16(q1));
        ((__nv_bfloat162*)g_kb)[(size_t)row * 32 + l] =
            __nv_bfloat162(__float2bfloat16(k0), __float2bfloat16(k1));
    }

    // ---- bias: lane l (<24) owns channel l; 4-accumulator dots ----
    if (l < 24) {
#pragma unroll
        for (int rr = 0; rr < 4; ++rr) {
            int r = w * 4 + rr;
            int row = row0 + r;
            int b = row >> 9, pos = row & 511;
            float p0 = 0.0f, p1 = 0.0f, p2 = 0.0f, p3 = 0.0f;
#pragma unroll
            for (int k = 0; k < 128; k += 16) {
                float4 x0 = *(float4*)&xs[r * 128 + k];
                float4 x1 = *(float4*)&xs[r * 128 + k + 4];
                float4 x2 = *(float4*)&xs[r * 128 + k + 8];
                float4 x3 = *(float4*)&xs[r * 128 + k + 12];
                p0 += x0.x * W2s[(k + 0) * 24 + l] + x0.y * W2s[(k + 1) * 24 + l]
                    + x0.z * W2s[(k + 2) * 24 + l] + x0.w * W2s[(k + 3) * 24 + l];
                p1 += x1.x * W2s[(k + 4) * 24 + l] + x1.y * W2s[(k + 5) * 24 + l]
                    + x1.z * W2s[(k + 6) * 24 + l] + x1.w * W2s[(k + 7) * 24 + l];
                p2 += x2.x * W2s[(k + 8) * 24 + l] + x2.y * W2s[(k + 9) * 24 + l]
                    + x2.z * W2s[(k + 10) * 24 + l] + x2.w * W2s[(k + 11) * 24 + l];
                p3 += x3.x * W2s[(k + 12) * 24 + l] + x3.y * W2s[(k + 13) * 24 + l]
                    + x3.z * W2s[(k + 14) * 24 + l] + x3.w * W2s[(k + 15) * 24 + l];
            }
            float p = (((p0 + p1) + (p2 + p3)) + b2s[l]) * 0.5f;
            int h = l >> 1;
            if (l & 1) g_bo[(b * 12 + h) * SEQ + pos] = p;
            else       g_be[(b * 12 + h) * SEQ + pos] = p;
        }
    }
}

// ============================================================================
// K2 v5 (frozen — measured 36.6us)
// ============================================================================
__global__ void __launch_bounds__(256, 4) k2_logits(const float* __restrict__ mask,
                                                    float* __restrict__ out) {
    __shared__ __nv_bfloat16 qs[32 * 72];
    __shared__ __nv_bfloat16 ks[64 * 72];
    __shared__ float bs[32 * 68];
    __shared__ float beS[12][64];
    __shared__ float boS[12][32];

    int tid = threadIdx.x;
    int b = blockIdx.z, m0 = blockIdx.y * 32, n0 = blockIdx.x * 64;

    {
        int m = tid >> 3, t = tid & 7;
        uint4 v = ((const uint4*)(g_qb + ((size_t)b * SEQ + m0 + m) * HS))[t];
        *(uint4*)(qs + m * 72 + t * 8) = v;
    }
#pragma unroll
    for (int i = tid; i < 512; i += 256) {
        int n = i >> 3, t = i & 7;
        uint4 v = ((const uint4*)(g_kb + ((size_t)b * SEQ + n0 + n) * HS))[t];
        *(uint4*)(ks + n * 72 + t * 8) = v;
    }
    for (int i = tid; i < 12 * 64; i += 256)
        beS[i >> 6][i & 63] = g_be[(b * 12 + (i >> 6)) * SEQ + n0 + (i & 63)];
    if (tid < 12 * 32)
        boS[tid >> 5][tid & 31] = g_bo[(b * 12 + (tid >> 5)) * SEQ + m0 + (tid & 31)];
    __syncthreads();

    {
        int w = tid >> 5;
        int mi = w & 1, ni = w >> 1;
        wmma::fragment<wmma::accumulator, 16, 16, 16, float> acc;
        wmma::fill_fragment(acc, 0.0f);
#pragma unroll
        for (int kd = 0; kd < 4; ++kd) {
            wmma::fragment<wmma::matrix_a, 16, 16, 16, __nv_bfloat16, wmma::row_major> fa;
            wmma::fragment<wmma::matrix_b, 16, 16, 16, __nv_bfloat16, wmma::col_major> fb;
            wmma::load_matrix_sync(fa, qs + mi * 16 * 72 + kd * 16, 72);
            wmma::load_matrix_sync(fb, ks + ni * 16 * 72 + kd * 16, 72);
            wmma::mma_sync(acc, fa, fb, acc);
        }
        wmma::store_matrix_sync(bs + mi * 16 * 68 + ni * 16, acc, 68,
                                wmma::mem_row_major);
    }
    __syncthreads();

    int mg = tid >> 4;
    int ng = tid & 15;

    float4 mnv = *(const float4*)&mask[b * SEQ + n0 + ng * 4];
    float mn4[4] = {mnv.x, mnv.y, mnv.z, mnv.w};
    float base[2][4];
#pragma unroll
    for (int i = 0; i < 2; ++i) {
        int gm = m0 + mg * 2 + i;
        float mm = mask[b * SEQ + gm];
        float4 dv = *(float4*)&bs[(mg * 2 + i) * 68 + ng * 4];
        float d4[4] = {dv.x, dv.y, dv.z, dv.w};
#pragma unroll
        for (int j = 0; j < 4; ++j) {
            int gn = n0 + ng * 4 + j;
            float pen = (1.0f - mm * mn4[j]) * NEG_BIG + ((gn < gm) ? NEG_BIG : 0.0f);
            base[i][j] = d4[j] * 0.125f - pen;
        }
    }

    float* optr = out + ((size_t)(b * 12) * SEQ + (m0 + mg * 2)) * SEQ + n0 + ng * 4;
#pragma unroll
    for (int h = 0; h < 12; ++h) {
        float4 be4 = *(float4*)&beS[h][ng * 4];
        float bo0 = boS[h][mg * 2];
        float bo1 = boS[h][mg * 2 + 1];
        float4 o0, o1;
        o0.x = base[0][0] + be4.x + bo0;
        o0.y = base[0][1] + be4.y + bo0;
        o0.z = base[0][2] + be4.z + bo0;
        o0.w = base[0][3] + be4.w + bo0;
        o1.x = base[1][0] + be4.x + bo1;
        o1.y = base[1][1] + be4.y + bo1;
        o1.z = base[1][2] + be4.z + bo1;
        o1.w = base[1][3] + be4.w + bo1;
        *(float4*)(optr + (size_t)h * SEQ * SEQ)       = o0;
        *(float4*)(optr + (size_t)h * SEQ * SEQ + SEQ) = o1;
    }
}

// no-ops: put k1_gemm at ncu's deterministic capture slot (launch #4)
__global__ void knop() {}

extern "C" void kernel_launch(void* const* d_in, const int* in_sizes, int n_in,
                              void* d_out, int out_size) {
    (void)in_sizes; (void)n_in; (void)out_size;
    const float* inp  = (const float*)d_in[0];
    const float* mask = (const float*)d_in[1];
    const float* W1   = (const float*)d_in[2];
    const float* b1   = (const float*)d_in[3];
    const float* W2   = (const float*)d_in[4];
    const float* b2   = (const float*)d_in[5];
    float* out = (float*)d_out;

    cudaFuncSetAttribute(k1_gemm, cudaFuncAttributeMaxDynamicSharedMemorySize, K1_DYN);

    knop<<<1, 32>>>();
    knop<<<1, 32>>>();
    convAW<<<4096 + 64, 256>>>((const float4*)inp, (const float4*)W1);
    k1_gemm<<<ROWS / 32, 256, K1_DYN>>>(b1, W2, b2);
    k2_logits<<<dim3(SEQ / 64, SEQ / 32, BB), 256>>>(mask, out);
}

// round 16
// speedup vs baseline: 1.0769x; 1.0769x over previous
#include <cuda_runtime.h>
#include <cuda_bf16.h>
#include <mma.h>
#include <cstdint>
#include <cstddef>

using namespace nvcuda;

#define BB 16
#define SEQ 512
#define HID 1024
#define C2 128          // 2*HEAD_SIZE
#define NHEADS 12
#define HS 64
#define ROWS (BB*SEQ)   // 8192
#define NEG_BIG 1000000000000.0f

// k1 smem layout:
//   Af  [32][68] fp32  per stage (8704 B; 272B rows: 16B-aligned, LDS-friendly)
//   Ws  [64][136] bf16 per stage (17408 B; 272B rows: conflict-free LDSM)
//   Ahs [32][72]  bf16 single    (4608 B; 144B rows: conflict-free LDSM)
#define AST 72
#define WST 136
#define AFST 68
#define AFBYTES (32 * AFST * 4)       // 8704
#define WBYTES  (64 * WST * 2)        // 17408
#define STAGE   (AFBYTES + WBYTES)    // 26112
#define AHS_OFF (2 * STAGE)           // 52224
#define K1_DYN  (2 * STAGE + 32 * AST * 2)   // 56832

// ---- scratch (device globals) ----
__device__ __nv_bfloat16 g_w1b[HID * C2];    // W1 bf16
__device__ __nv_bfloat16 g_qb[ROWS * HS];    // RoPE'd q, bf16
__device__ __nv_bfloat16 g_kb[ROWS * HS];    // RoPE'd k, bf16
__device__ float g_be[BB * NHEADS * SEQ];
__device__ float g_bo[BB * NHEADS * SEQ];

__device__ __forceinline__ uint32_t s2u(const void* p) {
    uint32_t a;
    asm("{ .reg .u64 t; cvta.to.shared.u64 t, %1; cvt.u32.u64 %0, t; }"
        : "=r"(a) : "l"(p));
    return a;
}
#define CP16(dst_u32, src_ptr) \
    asm volatile("cp.async.ca.shared.global [%0], [%1], 16;" \
                 :: "r"(dst_u32), "l"(src_ptr) : "memory")
#define CPCOMMIT() asm volatile("cp.async.commit_group;" ::: "memory")
#define CPWAIT1()  asm volatile("cp.async.wait_group 1;" ::: "memory")
#define CPWAIT0()  asm volatile("cp.async.wait_group 0;" ::: "memory")

__device__ __forceinline__ uint32_t packbf2(float a, float b) {
    __nv_bfloat162 h(__float2bfloat16(a), __float2bfloat16(b));
    return *(uint32_t*)&h;
}

// ========================================================================
// convW: W1 fp32 [1024][128] -> bf16 (131072 floats, 64 blocks)
// ========================================================================
__global__ void __launch_bounds__(256) convW(const float4* __restrict__ W1) {
    size_t i = (size_t)blockIdx.x * 256 + threadIdx.x;   // uint4 index
    float4 v0 = W1[2 * i];
    float4 v1 = W1[2 * i + 1];
    uint4 o;
    o.x = packbf2(v0.x, v0.y);
    o.y = packbf2(v0.z, v0.w);
    o.z = packbf2(v1.x, v1.y);
    o.w = packbf2(v1.z, v1.w);
    ((uint4*)g_w1b)[i] = o;
}

// ========================================================================
// k1_gemm v5 (R12 structure + in-loop A conversion):
// per 32-row tile (grid 256), 16 chunks of K=64:
//   cp.async: A fp32 chunk + W bf16 chunk (2-stage)
//   convert Af -> Ahs (bf16), then 8x HMMA
// epilogue: x=A@W1+b1 -> RoPE -> g_qb/g_kb ; bias -> g_be/g_bo
// ========================================================================
__global__ void __launch_bounds__(256) k1_gemm(const float* __restrict__ A,
                                               const float* __restrict__ b1,
                                               const float* __restrict__ W2,
                                               const float* __restrict__ b2) {
    extern __shared__ __align__(16) char sm[];
    float* xs = (float*)sm;                    // [32][128] f32, epilogue only
    __nv_bfloat16* Ahs = (__nv_bfloat16*)(sm + AHS_OFF);
    __shared__ float W2s[128 * 24];
    __shared__ float b1s[128];
    __shared__ float b2s[24];

    int tid = threadIdx.x, w = tid >> 5, l = tid & 31;
    int row0 = blockIdx.x * 32;
    uint32_t sbase = s2u(sm);

    if (tid < 128) b1s[tid] = b1[tid];
    if (tid < 24)  b2s[tid] = b2[tid];
    for (int i = tid; i < 3072; i += 256) W2s[i] = W2[i];

    int wm = (w & 1) * 16;
    int wn = (w >> 1) * 32;

    // cp.async coordinates
    int ar = tid >> 4, aseg = tid & 15;        // A fp32: 32 rows x 16 segs(16B)

    wmma::fragment<wmma::accumulator, 16, 16, 16, float> acc[2];
    wmma::fill_fragment(acc[0], 0.0f);
    wmma::fill_fragment(acc[1], 0.0f);

    auto issue = [&](int kc, int s) {
        uint32_t ab = sbase + (uint32_t)s * STAGE;
        uint32_t wb = ab + AFBYTES;
        // A fp32: 512 CP16 (2/thread): rows 32, 16 segs of 4 floats
#pragma unroll
        for (int s2 = 0; s2 < 2; ++s2) {
            int idx = tid + s2 * 256;
            int r = idx >> 4, seg = idx & 15;
            CP16(ab + (uint32_t)(r * AFST + seg * 4) * 4,
                 A + (size_t)(row0 + r) * HID + kc + seg * 4);
        }
        // W bf16: 1024 CP16 (4/thread)
#pragma unroll
        for (int s4 = 0; s4 < 4; ++s4) {
            int idx = tid + s4 * 256;
            int r = idx >> 4, seg = idx & 15;
            CP16(wb + (uint32_t)(r * WST + seg * 8) * 2,
                 g_w1b + (size_t)(kc + r) * C2 + seg * 8);
        }
        CPCOMMIT();
    };

    issue(0, 0);
    for (int c = 0; c < 16; ++c) {
        if (c < 15) { issue((c + 1) * 64, (c + 1) & 1); CPWAIT1(); }
        else        { CPWAIT0(); }
        __syncthreads();   // chunk c data arrived everywhere; mma(c-1) done
        // ---- convert Af(c) -> Ahs: 2048 floats, 8/thread ----
        {
            const float* Af = (const float*)(sm + (c & 1) * STAGE);
#pragma unroll
            for (int s2 = 0; s2 < 2; ++s2) {
                int idx = tid + s2 * 256;
                int r = idx >> 4, seg = idx & 15;
                float4 v = *(const float4*)(Af + r * AFST + seg * 4);
                uint2 o;
                o.x = packbf2(v.x, v.y);
                o.y = packbf2(v.z, v.w);
                *(uint2*)(Ahs + r * AST + seg * 4) = o;
            }
        }
        __syncthreads();   // Ahs complete
        const __nv_bfloat16* Wb =
            (const __nv_bfloat16*)(sm + (c & 1) * STAGE + AFBYTES);
#pragma unroll
        for (int ks = 0; ks < 4; ++ks) {
            wmma::fragment<wmma::matrix_a, 16, 16, 16, __nv_bfloat16, wmma::row_major> fa;
            wmma::load_matrix_sync(fa, Ahs + wm * AST + ks * 16, AST);
#pragma unroll
            for (int nt = 0; nt < 2; ++nt) {
                wmma::fragment<wmma::matrix_b, 16, 16, 16, __nv_bfloat16, wmma::row_major> fb;
                wmma::load_matrix_sync(fb, Wb + ks * 16 * WST + wn + nt * 16, WST);
                wmma::mma_sync(acc[nt], fa, fb, acc[nt]);
            }
        }
    }
    __syncthreads();

    // ---- epilogue: frags -> xs, add b1 ----
    wmma::store_matrix_sync(xs + wm * C2 + wn,      acc[0], C2, wmma::mem_row_major);
    wmma::store_matrix_sync(xs + wm * C2 + wn + 16, acc[1], C2, wmma::mem_row_major);
    __syncthreads();
#pragma unroll
    for (int s = 0; s < 4; ++s) {
        int i = tid + s * 256;
        int r = i >> 5, c4 = i & 31;
        float4 v  = *(float4*)&xs[r * C2 + c4 * 4];
        float4 bv = *(float4*)&b1s[c4 * 4];
        v.x += bv.x; v.y += bv.y; v.z += bv.z; v.w += bv.w;
        *(float4*)&xs[r * C2 + c4 * 4] = v;
    }
    __syncthreads();

    // ---- RoPE: warp w owns rows w*4..w*4+3 ----
    float inv = exp2f(-(float)l * 0.41524101186091903f);
#pragma unroll
    for (int rr = 0; rr < 4; ++rr) {
        int r = w * 4 + rr;
        int row = row0 + r;
        int pos = row & 511;
        float4 xv = *(float4*)&xs[r * 128 + l * 4];
        float sn, cs;
        sincosf((float)pos * inv, &sn, &cs);
        float q0 = xv.x * cs - xv.z * sn;
        float q1 = xv.z * cs + xv.x * sn;
        float k0 = xv.y * cs - xv.w * sn;
        float k1 = xv.w * cs + xv.y * sn;
        ((__nv_bfloat162*)g_qb)[(size_t)row * 32 + l] =
            __nv_bfloat162(__float2bfloat16(q0), __float2bfloat16(q1));
        ((__nv_bfloat162*)g_kb)[(size_t)row * 32 + l] =
            __nv_bfloat162(__float2bfloat16(k0), __float2bfloat16(k1));
    }

    // ---- bias: lane l (<24) owns channel l; 4-accumulator dots ----
    if (l < 24) {
#pragma unroll
        for (int rr = 0; rr < 4; ++rr) {
            int r = w * 4 + rr;
            int row = row0 + r;
            int b = row >> 9, pos = row & 511;
            float p0 = 0.0f, p1 = 0.0f, p2 = 0.0f, p3 = 0.0f;
#pragma unroll
            for (int k = 0; k < 128; k += 16) {
                float4 x0 = *(float4*)&xs[r * 128 + k];
                float4 x1 = *(float4*)&xs[r * 128 + k + 4];
                float4 x2 = *(float4*)&xs[r * 128 + k + 8];
                float4 x3 = *(float4*)&xs[r * 128 + k + 12];
                p0 += x0.x * W2s[(k + 0) * 24 + l] + x0.y * W2s[(k + 1) * 24 + l]
                    + x0.z * W2s[(k + 2) * 24 + l] + x0.w * W2s[(k + 3) * 24 + l];
                p1 += x1.x * W2s[(k + 4) * 24 + l] + x1.y * W2s[(k + 5) * 24 + l]
                    + x1.z * W2s[(k + 6) * 24 + l] + x1.w * W2s[(k + 7) * 24 + l];
                p2 += x2.x * W2s[(k + 8) * 24 + l] + x2.y * W2s[(k + 9) * 24 + l]
                    + x2.z * W2s[(k + 10) * 24 + l] + x2.w * W2s[(k + 11) * 24 + l];
                p3 += x3.x * W2s[(k + 12) * 24 + l] + x3.y * W2s[(k + 13) * 24 + l]
                    + x3.z * W2s[(k + 14) * 24 + l] + x3.w * W2s[(k + 15) * 24 + l];
            }
            float p = (((p0 + p1) + (p2 + p3)) + b2s[l]) * 0.5f;
            int h = l >> 1;
            if (l & 1) g_bo[(b * 12 + h) * SEQ + pos] = p;
            else       g_be[(b * 12 + h) * SEQ + pos] = p;
        }
    }
}

// ============================================================================
// K2 v5 (frozen — measured 36.6us)
// ============================================================================
__global__ void __launch_bounds__(256, 4) k2_logits(const float* __restrict__ mask,
                                                    float* __restrict__ out) {
    __shared__ __nv_bfloat16 qs[32 * 72];
    __shared__ __nv_bfloat16 ks[64 * 72];
    __shared__ float bs[32 * 68];
    __shared__ float beS[12][64];
    __shared__ float boS[12][32];

    int tid = threadIdx.x;
    int b = blockIdx.z, m0 = blockIdx.y * 32, n0 = blockIdx.x * 64;

    {
        int m = tid >> 3, t = tid & 7;
        uint4 v = ((const uint4*)(g_qb + ((size_t)b * SEQ + m0 + m) * HS))[t];
        *(uint4*)(qs + m * 72 + t * 8) = v;
    }
#pragma unroll
    for (int i = tid; i < 512; i += 256) {
        int n = i >> 3, t = i & 7;
        uint4 v = ((const uint4*)(g_kb + ((size_t)b * SEQ + n0 + n) * HS))[t];
        *(uint4*)(ks + n * 72 + t * 8) = v;
    }
    for (int i = tid; i < 12 * 64; i += 256)
        beS[i >> 6][i & 63] = g_be[(b * 12 + (i >> 6)) * SEQ + n0 + (i & 63)];
    if (tid < 12 * 32)
        boS[tid >> 5][tid & 31] = g_bo[(b * 12 + (tid >> 5)) * SEQ + m0 + (tid & 31)];
    __syncthreads();

    {
        int w = tid >> 5;
        int mi = w & 1, ni = w >> 1;
        wmma::fragment<wmma::accumulator, 16, 16, 16, float> acc;
        wmma::fill_fragment(acc, 0.0f);
#pragma unroll
        for (int kd = 0; kd < 4; ++kd) {
            wmma::fragment<wmma::matrix_a, 16, 16, 16, __nv_bfloat16, wmma::row_major> fa;
            wmma::fragment<wmma::matrix_b, 16, 16, 16, __nv_bfloat16, wmma::col_major> fb;
            wmma::load_matrix_sync(fa, qs + mi * 16 * 72 + kd * 16, 72);
            wmma::load_matrix_sync(fb, ks + ni * 16 * 72 + kd * 16, 72);
            wmma::mma_sync(acc, fa, fb, acc);
        }
        wmma::store_matrix_sync(bs + mi * 16 * 68 + ni * 16, acc, 68,
                                wmma::mem_row_major);
    }
    __syncthreads();

    int mg = tid >> 4;
    int ng = tid & 15;

    float4 mnv = *(const float4*)&mask[b * SEQ + n0 + ng * 4];
    float mn4[4] = {mnv.x, mnv.y, mnv.z, mnv.w};
    float base[2][4];
#pragma unroll
    for (int i = 0; i < 2; ++i) {
        int gm = m0 + mg * 2 + i;
        float mm = mask[b * SEQ + gm];
        float4 dv = *(float4*)&bs[(mg * 2 + i) * 68 + ng * 4];
        float d4[4] = {dv.x, dv.y, dv.z, dv.w};
#pragma unroll
        for (int j = 0; j < 4; ++j) {
            int gn = n0 + ng * 4 + j;
            float pen = (1.0f - mm * mn4[j]) * NEG_BIG + ((gn < gm) ? NEG_BIG : 0.0f);
            base[i][j] = d4[j] * 0.125f - pen;
        }
    }

    float* optr = out + ((size_t)(b * 12) * SEQ + (m0 + mg * 2)) * SEQ + n0 + ng * 4;
#pragma unroll
    for (int h = 0; h < 12; ++h) {
        float4 be4 = *(float4*)&beS[h][ng * 4];
        float bo0 = boS[h][mg * 2];
        float bo1 = boS[h][mg * 2 + 1];
        float4 o0, o1;
        o0.x = base[0][0] + be4.x + bo0;
        o0.y = base[0][1] + be4.y + bo0;
        o0.z = base[0][2] + be4.z + bo0;
        o0.w = base[0][3] + be4.w + bo0;
        o1.x = base[1][0] + be4.x + bo1;
        o1.y = base[1][1] + be4.y + bo1;
        o1.z = base[1][2] + be4.z + bo1;
        o1.w = base[1][3] + be4.w + bo1;
        *(float4*)(optr + (size_t)h * SEQ * SEQ)       = o0;
        *(float4*)(optr + (size_t)h * SEQ * SEQ + SEQ) = o1;
    }
}

// no-ops: keep k1_gemm at ncu's deterministic capture slot (launch #4)
__global__ void knop() {}

extern "C" void kernel_launch(void* const* d_in, const int* in_sizes, int n_in,
                              void* d_out, int out_size) {
    (void)in_sizes; (void)n_in; (void)out_size;
    const float* inp  = (const float*)d_in[0];
    const float* mask = (const float*)d_in[1];
    const float* W1   = (const float*)d_in[2];
    const float* b1   = (const float*)d_in[3];
    const float* W2   = (const float*)d_in[4];
    const float* b2   = (const float*)d_in[5];
    float* out = (float*)d_out;

    cudaFuncSetAttribute(k1_gemm, cudaFuncAttributeMaxDynamicSharedMemorySize, K1_DYN);

    knop<<<1, 32>>>();
    knop<<<1, 32>>>();
    convW<<<64, 256>>>((const float4*)W1);
    k1_gemm<<<ROWS / 32, 256, K1_DYN>>>(inp, b1, W2, b2);
    k2_logits<<<dim3(SEQ / 64, SEQ / 32, BB), 256>>>(mask, out);
}